// round 9
// baseline (speedup 1.0000x reference)
#include <cuda_runtime.h>
#include <cuda_bf16.h>
#include <math.h>

// Problem constants
#define BB 64
#define SS 128
#define CC 32
#define DD 512
#define VV 20000
#define BS (BB*SS)          // 8192
#define G4D (4*DD)          // 2048

// ---------------- device scratch (allocation-free rule: __device__ globals) ----
__device__ float g_x[BS*DD];           // 16 MB  visit embeddings summed
__device__ float g_tf[BS*DD];          // 16 MB  time features
__device__ float g_ux[(size_t)BS*G4D]; // 64 MB  input projection
__device__ float g_h[2][BB*DD];        // ping-pong hidden
__device__ float g_c[2][BB*DD];        // ping-pong cell
__device__ float g_hs[(size_t)BB*SS*DD]; // 16 MB all hidden states
__device__ unsigned g_flags[128];      // per-CTA step counters
__device__ unsigned g_release[2][32];  // per-group release words (padded)

// ---------------- f32x2 packed helpers (Blackwell) ----------------------------
__device__ __forceinline__ unsigned long long ffma2(unsigned long long a,
                                                    unsigned long long b,
                                                    unsigned long long c) {
    unsigned long long d;
    asm("fma.rn.f32x2 %0, %1, %2, %3;" : "=l"(d) : "l"(a), "l"(b), "l"(c));
    return d;
}
__device__ __forceinline__ unsigned long long pack2(float lo, float hi) {
    unsigned long long r;
    asm("mov.b64 %0, {%1, %2};" : "=l"(r) : "f"(lo), "f"(hi));
    return r;
}
__device__ __forceinline__ float2 unpack2(unsigned long long v) {
    float2 r;
    asm("mov.b64 {%0, %1}, %2;" : "=f"(r.x), "=f"(r.y) : "l"(v));
    return r;
}
union F4U { float4 f; unsigned long long u[2]; };

__device__ __forceinline__ float sigmoidf_(float x) { return 1.0f / (1.0f + expf(-x)); }

__device__ __forceinline__ void cpasync16(unsigned saddr, const float* g) {
    asm volatile("cp.async.cg.shared.global [%0], [%1], 16;" :: "r"(saddr), "l"(g));
}
__device__ __forceinline__ void cpasync_commit() {
    asm volatile("cp.async.commit_group;");
}
template<int N> __device__ __forceinline__ void cpasync_wait() {
    asm volatile("cp.async.wait_group %0;" :: "n"(N));
}

// ---------------- kernel: zero h0/c0 + reset barrier state ---------------------
__global__ void k_zero() {
    int i = blockIdx.x * blockDim.x + threadIdx.x;
    if (i < BB*DD) { g_h[0][i] = 0.0f; g_c[0][i] = 0.0f; }
    if (i < 128) g_flags[i] = 0u;
    if (i < 64) ((unsigned*)g_release)[i] = 0u;
}

// ---------------- kernel: gather + sum embeddings ------------------------------
__global__ __launch_bounds__(128) void k_gather(const float* __restrict__ emb,
                                                const int* __restrict__ seqs) {
    int bs = blockIdx.x;
    __shared__ int sidx[CC];
    if (threadIdx.x < CC) sidx[threadIdx.x] = seqs[bs*CC + threadIdx.x];
    __syncthreads();
    int d4 = threadIdx.x;  // 0..127
    float4 acc = make_float4(0.f, 0.f, 0.f, 0.f);
#pragma unroll 8
    for (int c = 0; c < CC; c++) {
        const float4* row = (const float4*)(emb + (size_t)sidx[c] * DD);
        float4 v = __ldg(row + d4);
        acc.x += v.x; acc.y += v.y; acc.z += v.z; acc.w += v.w;
    }
    ((float4*)(g_x + (size_t)bs * DD))[d4] = acc;
}

// ---------------- kernel: time feature ----------------------------------------
__global__ __launch_bounds__(512) void k_tf(const float* __restrict__ tstep,
                                            const float* __restrict__ selw,
                                            const float* __restrict__ selb,
                                            const float* __restrict__ timew,
                                            const float* __restrict__ timeb) {
    int b  = blockIdx.x >> 1;
    int s0 = (blockIdx.x & 1) * 64;
    int d  = threadIdx.x;
    float tw[64];
    const float4* twp = (const float4*)(timew + (size_t)d * 64);
#pragma unroll
    for (int i = 0; i < 16; i++) {
        float4 v = __ldg(twp + i);
        tw[i*4+0] = v.x; tw[i*4+1] = v.y; tw[i*4+2] = v.z; tw[i*4+3] = v.w;
    }
    float tb = timeb[d];
    __shared__ float feat[64];
    for (int si = 0; si < 64; si++) {
        int s = s0 + si;
        if (d < 64) {
            float t = tstep[b*SS + s] * (1.0f / 180.0f);
            float v = t * selw[d] + selb[d];
            feat[d] = 1.0f - tanhf(v * v);
        }
        __syncthreads();
        float acc = tb;
#pragma unroll
        for (int k = 0; k < 64; k++) acc += feat[k] * tw[k];
        g_tf[((size_t)b*SS + s) * DD + d] = acc;
        __syncthreads();
    }
}

// ---------------- kernel: ux = x @ U^T + Ub  (SGEMM 8192x2048x512, f32x2) ------
#define TM 128
#define TN 128
#define TK 16
__global__ __launch_bounds__(256, 2) void k_gemm_ux(const float* __restrict__ U,
                                                    const float* __restrict__ Ub) {
    __shared__ float As[2][TK][TM + 4];
    __shared__ float Bs[2][TK][TN + 4];
    int m0 = blockIdx.y * TM;
    int n0 = blockIdx.x * TN;
    int t = threadIdx.x;
    int lrow = t >> 2;          // 0..63
    int lcol = (t & 3) * 4;     // 0,4,8,12

    const float* Aptr = g_x + (size_t)(m0 + lrow) * DD + lcol;
    const float* Bptr = U   + (size_t)(n0 + lrow) * DD + lcol;

    float4 ra[2], rb[2];
    ra[0] = *(const float4*)(Aptr);
    ra[1] = *(const float4*)(Aptr + 64*DD);
    rb[0] = *(const float4*)(Bptr);
    rb[1] = *(const float4*)(Bptr + 64*DD);

    int warp = t >> 5;
    int wm   = warp >> 1;
    int wn   = warp & 1;
    int lane = t & 31;
    int lm   = lane >> 3;
    int ln   = lane & 7;
    int ma   = wm*32 + lm*4;
    int nb   = wn*64 + ln*4;

    unsigned long long acc[4][8];
#pragma unroll
    for (int mp = 0; mp < 4; mp++)
#pragma unroll
        for (int nn = 0; nn < 8; nn++) acc[mp][nn] = 0ull;

#pragma unroll
    for (int i = 0; i < 2; i++) {
        int r = lrow + i*64;
        As[0][lcol+0][r] = ra[i].x; As[0][lcol+1][r] = ra[i].y;
        As[0][lcol+2][r] = ra[i].z; As[0][lcol+3][r] = ra[i].w;
        Bs[0][lcol+0][r] = rb[i].x; Bs[0][lcol+1][r] = rb[i].y;
        Bs[0][lcol+2][r] = rb[i].z; Bs[0][lcol+3][r] = rb[i].w;
    }
    __syncthreads();

    const int NT = DD / TK;  // 32
    for (int kt = 0; kt < NT; kt++) {
        if (kt < NT - 1) {
            const float* ap = Aptr + (kt+1)*TK;
            const float* bp = Bptr + (kt+1)*TK;
            ra[0] = *(const float4*)(ap);
            ra[1] = *(const float4*)(ap + 64*DD);
            rb[0] = *(const float4*)(bp);
            rb[1] = *(const float4*)(bp + 64*DD);
        }
        int buf = kt & 1;
#pragma unroll
        for (int k = 0; k < TK; k++) {
            F4U a0, a1, b0, b1;
            a0.f = *(const float4*)&As[buf][k][ma];
            a1.f = *(const float4*)&As[buf][k][ma+16];
            b0.f = *(const float4*)&Bs[buf][k][nb];
            b1.f = *(const float4*)&Bs[buf][k][nb+32];
            unsigned long long ap2[4] = { a0.u[0], a0.u[1], a1.u[0], a1.u[1] };
            float bv[8] = {b0.f.x,b0.f.y,b0.f.z,b0.f.w,b1.f.x,b1.f.y,b1.f.z,b1.f.w};
            unsigned long long bb2[8];
#pragma unroll
            for (int nn = 0; nn < 8; nn++) bb2[nn] = pack2(bv[nn], bv[nn]);
#pragma unroll
            for (int mp = 0; mp < 4; mp++)
#pragma unroll
                for (int nn = 0; nn < 8; nn++)
                    acc[mp][nn] = ffma2(ap2[mp], bb2[nn], acc[mp][nn]);
        }
        if (kt < NT - 1) {
            __syncthreads();
            int nbuf = buf ^ 1;
#pragma unroll
            for (int i = 0; i < 2; i++) {
                int r = lrow + i*64;
                As[nbuf][lcol+0][r] = ra[i].x; As[nbuf][lcol+1][r] = ra[i].y;
                As[nbuf][lcol+2][r] = ra[i].z; As[nbuf][lcol+3][r] = ra[i].w;
                Bs[nbuf][lcol+0][r] = rb[i].x; Bs[nbuf][lcol+1][r] = rb[i].y;
                Bs[nbuf][lcol+2][r] = rb[i].z; Bs[nbuf][lcol+3][r] = rb[i].w;
            }
            __syncthreads();
        }
    }

    float ub[8];
#pragma unroll
    for (int nn = 0; nn < 8; nn++)
        ub[nn] = Ub[n0 + nb + (nn>>2)*32 + (nn&3)];
#pragma unroll
    for (int mp = 0; mp < 4; mp++) {
#pragma unroll
        for (int e = 0; e < 2; e++) {
            int m = m0 + ma + (mp>>1)*16 + (mp&1)*2 + e;
            float* Crow = g_ux + (size_t)m * G4D + n0;
#pragma unroll
            for (int nc = 0; nc < 2; nc++) {
                float4 v;
                float2 p0 = unpack2(acc[mp][nc*4+0]);
                float2 p1 = unpack2(acc[mp][nc*4+1]);
                float2 p2 = unpack2(acc[mp][nc*4+2]);
                float2 p3 = unpack2(acc[mp][nc*4+3]);
                v.x = (e ? p0.y : p0.x) + ub[nc*4+0];
                v.y = (e ? p1.y : p1.x) + ub[nc*4+1];
                v.z = (e ? p2.y : p2.x) + ub[nc*4+2];
                v.w = (e ? p3.y : p3.x) + ub[nc*4+3];
                *(float4*)(Crow + nb + nc*32) = v;
            }
        }
    }
}

// ---------------- persistent recurrent kernel (all 128 steps) -------------------
// 128 CTAs = 64 jg x 2 bg. 512 threads, k-split: threads t and t+256 compute the
// same (j,b) output over k halves [0,256) and [256,512). Each half owns 2 h/c
// chunks (own cp.async groups, own named barrier) -> 16 warps, 4/SMSP latency
// hiding, halves fully concurrent. Once-per-step smem pair-reduction.
#define NCTA 128
#define JPC 8
#define BPC 32
#define CH 128
#define NCH 4
#define WPAD 516
#define HPAD2 132
#define HSZ (BPC*HPAD2)            // 4224 floats per chunk buffer per array
#define STEP_SMEM ((8*WPAD + 32*WPAD + 2*NCH*HSZ) * 4)   // 217728 B

__global__ __launch_bounds__(512) void k_rnn(
        const float* __restrict__ Wall, const float* __restrict__ Wallb,
        const float* __restrict__ Wd,   const float* __restrict__ Wdb) {
    extern __shared__ float sm[];
    float* WD  = sm;                       // 8*516
    float* WA  = WD + 8*WPAD;              // 32*516
    float* HSm = WA + 32*WPAD;             // NCH bufs * 32*132
    float* CSm = HSm + NCH*HSZ;            // NCH bufs * 32*132

    unsigned HSu = (unsigned)__cvta_generic_to_shared(HSm);
    unsigned CSu = (unsigned)__cvta_generic_to_shared(CSm);

    int t  = threadIdx.x;
    int kh = t >> 8;                      // k-half 0/1
    int lt = t & 255;                     // lane within half
    int jg = blockIdx.x & 63;
    int bg = blockIdx.x >> 6;
    int j0 = jg * JPC;
    int b0 = bg * BPC;

    // ---- load weights into smem ONCE (padded rows, 512 threads) ----
#pragma unroll
    for (int i = 0; i < 2; i++) {
        int fi = t + i*512;               // 0..1023 float4
        int row = fi >> 7, k4 = fi & 127;
        float4 v = *(const float4*)(Wd + (size_t)(j0 + row) * DD + k4*4);
        *(float4*)(WD + row*WPAD + k4*4) = v;
    }
#pragma unroll
    for (int i = 0; i < 8; i++) {
        int fi = t + i*512;               // 0..4095 float4
        int r = fi >> 7, k4 = fi & 127;
        int g = r >> 3, jj2 = r & 7;
        float4 v = *(const float4*)(Wall + (size_t)(g*DD + j0 + jj2) * DD + k4*4);
        *(float4*)(WA + r*WPAD + k4*4) = v;
    }
    __syncthreads();                      // weights visible to all

    int jj = lt & 7;
    int b  = lt >> 3;                     // local batch row 0..31
    int j  = j0 + jj;
    int gb = b0 + b;                      // global batch row
    int cj = j >> 7;                      // chunk holding column j of c
    int jcid = j & 127;

    // per-thread biases (only lower half uses them)
    float wdb  = __ldg(Wdb + j);
    float wab0 = __ldg(Wallb + 0*DD + j);
    float wab1 = __ldg(Wallb + 1*DD + j);
    float wab2 = __ldg(Wallb + 2*DD + j);
    float wab3 = __ldg(Wallb + 3*DD + j);

    const float* WDrow  = WD + jj*WPAD;
    const float* WArow0 = WA + (0*JPC + jj)*WPAD;
    const float* WArow1 = WA + (1*JPC + jj)*WPAD;
    const float* WArow2 = WA + (2*JPC + jj)*WPAD;
    const float* WArow3 = WA + (3*JPC + jj)*WPAD;

    unsigned long long* red = (unsigned long long*)HSm;  // reduction area (chunk0, reused)

    float tfv = 0.f, ux0 = 0.f, ux1 = 0.f, ux2 = 0.f, ux3 = 0.f;
    if (kh == 0) {
        tfv = __ldg(g_tf + ((size_t)gb * SS + 0) * DD + j);
        const float* uxr = g_ux + ((size_t)gb * SS + 0) * G4D;
        ux0 = __ldg(uxr + 0*DD + j);
        ux1 = __ldg(uxr + 1*DD + j);
        ux2 = __ldg(uxr + 2*DD + j);
        ux3 = __ldg(uxr + 3*DD + j);
    }

    for (int s = 0; s < SS; s++) {
        const float* h_in = g_h[s & 1];
        const float* c_in = g_c[s & 1];
        float* h_out = g_h[(s + 1) & 1];
        float* c_out = g_c[(s + 1) & 1];
        size_t bsoff = ((size_t)gb * SS + s);

        // issue OWN half's 2 chunks (each: 8 cp.async per thread)
#pragma unroll
        for (int cc = 0; cc < 2; cc++) {
            int ch = kh*2 + cc;
#pragma unroll
            for (int i = 0; i < 4; i++) {
                int fi = lt + i*256; int bb = fi >> 5, k4 = fi & 31;
                unsigned so = (unsigned)(((ch*BPC + bb)*HPAD2 + k4*4) * 4);
                cpasync16(HSu + so, h_in + (size_t)(b0+bb)*DD + ch*CH + k4*4);
                cpasync16(CSu + so, c_in + (size_t)(b0+bb)*DD + ch*CH + k4*4);
            }
            cpasync_commit();
        }

        unsigned long long accd = 0ull, acc[4] = {0ull, 0ull, 0ull, 0ull};
        float cprev = 0.0f;

#pragma unroll
        for (int cc = 0; cc < 2; cc++) {
            int ch = kh*2 + cc;
            if (cc == 0) cpasync_wait<1>(); else cpasync_wait<0>();
            // half-CTA named barrier: writers of this chunk are exactly this half
            if (kh == 0) { asm volatile("bar.sync 1, 256;" ::: "memory"); }
            else         { asm volatile("bar.sync 2, 256;" ::: "memory"); }
            const float* HSrow = HSm + ch*HSZ + b*HPAD2;
            const float* CSrow = CSm + ch*HSZ + b*HPAD2;
            if (ch == cj) cprev = CSrow[jcid];
            int wo = ch * CH;
#pragma unroll
            for (int k4 = 0; k4 < 32; k4++) {
                F4U hv, cv, wd, w0, w1, w2, w3;
                hv.f = *(const float4*)(HSrow + k4*4);
                cv.f = *(const float4*)(CSrow + k4*4);
                wd.f = *(const float4*)(WDrow  + wo + k4*4);
                w0.f = *(const float4*)(WArow0 + wo + k4*4);
                w1.f = *(const float4*)(WArow1 + wo + k4*4);
                w2.f = *(const float4*)(WArow2 + wo + k4*4);
                w3.f = *(const float4*)(WArow3 + wo + k4*4);
                accd   = ffma2(cv.u[0], wd.u[0], accd);
                accd   = ffma2(cv.u[1], wd.u[1], accd);
                acc[0] = ffma2(hv.u[0], w0.u[0], acc[0]);
                acc[0] = ffma2(hv.u[1], w0.u[1], acc[0]);
                acc[1] = ffma2(hv.u[0], w1.u[0], acc[1]);
                acc[1] = ffma2(hv.u[1], w1.u[1], acc[1]);
                acc[2] = ffma2(hv.u[0], w2.u[0], acc[2]);
                acc[2] = ffma2(hv.u[1], w2.u[1], acc[2]);
                acc[3] = ffma2(hv.u[0], w3.u[0], acc[3]);
                acc[3] = ffma2(hv.u[1], w3.u[1], acc[3]);
            }
        }

        // ---- pair reduction (t, t+256) via smem ----
        __syncthreads();
        if (kh == 1) {
            int base = lt * 6;
            red[base+0] = accd;
            red[base+1] = acc[0];
            red[base+2] = acc[1];
            red[base+3] = acc[2];
            red[base+4] = acc[3];
            red[base+5] = (unsigned long long)__float_as_uint(cprev);
        }
        __syncthreads();

        if (kh == 0) {
            int base = lt * 6;
            float2 rd = unpack2(red[base+0]);
            float2 r0 = unpack2(red[base+1]);
            float2 r1 = unpack2(red[base+2]);
            float2 r2 = unpack2(red[base+3]);
            float2 r3 = unpack2(red[base+4]);
            float up_cprev = __uint_as_float((unsigned)red[base+5]);
            if (cj >= 2) cprev = up_cprev;

            float2 vd = unpack2(accd);
            float cs1 = tanhf(vd.x + vd.y + rd.x + rd.y + wdb);
            float2 v0 = unpack2(acc[0]);
            float2 v1 = unpack2(acc[1]);
            float2 v2 = unpack2(acc[2]);
            float2 v3 = unpack2(acc[3]);
            float fg = sigmoidf_(v0.x + v0.y + r0.x + r0.y + wab0 + ux0);
            float ig = sigmoidf_(v1.x + v1.y + r1.x + r1.y + wab1 + ux1);
            float og = sigmoidf_(v2.x + v2.y + r2.x + r2.y + wab2 + ux2);
            float ct = sigmoidf_(v3.x + v3.y + r3.x + r3.y + wab3 + ux3);

            float cadj  = cprev + cs1 * (tfv - 1.0f);
            float cn    = fg * cadj + ig * ct;
            float hn    = og * tanhf(cn);
            c_out[(size_t)gb*DD + j] = cn;
            h_out[(size_t)gb*DD + j] = hn;
            g_hs[bsoff * DD + j] = hn;
        }

        if (s < SS - 1) {
            // prefetch next step's tf/ux (lower half only)
            if (kh == 0) {
                size_t bsoff1 = bsoff + 1;
                tfv = __ldg(g_tf + bsoff1 * DD + j);
                const float* uxr1 = g_ux + bsoff1 * G4D;
                ux0 = __ldg(uxr1 + 0*DD + j);
                ux1 = __ldg(uxr1 + 1*DD + j);
                ux2 = __ldg(uxr1 + 2*DD + j);
                ux3 = __ldg(uxr1 + 3*DD + j);
            }

            // ---- half-grid barrier for group bg (64 CTAs), no atomics ----
            __syncthreads();                      // all stores of this CTA issued
            if (t == 0) {
                __threadfence();                  // release this CTA's h/c stores
                *(volatile unsigned*)&g_flags[blockIdx.x] = (unsigned)(s + 1);
            }
            if (jg == 0) {
                if (t < 64) {
                    const volatile unsigned* f = (const volatile unsigned*)&g_flags[bg*64 + t];
                    while (*f < (unsigned)(s + 1)) { }
                    __threadfence();              // acquire
                }
                __syncthreads();
                if (t == 0) {
                    *(volatile unsigned*)&g_release[bg][0] = (unsigned)(s + 1);
                }
            } else {
                if (t == 0) {
                    const volatile unsigned* r = (const volatile unsigned*)&g_release[bg][0];
                    while (*r < (unsigned)(s + 1)) { }
                    __threadfence();              // acquire
                }
                __syncthreads();
            }
        }
    }
}

// ---------------- kernel: max-pool over S + output head ------------------------
__global__ __launch_bounds__(512) void k_pool(const float* __restrict__ ow,
                                              const float* __restrict__ ob,
                                              float* __restrict__ out) {
    int b = blockIdx.x;
    int d = threadIdx.x;
    const float* p = g_hs + (size_t)b * SS * DD + d;
    float m = -3.0e38f;
#pragma unroll 8
    for (int s = 0; s < SS; s++) m = fmaxf(m, p[(size_t)s * DD]);
    float s0 = m * ow[d];
    float s1 = m * ow[DD + d];
    __shared__ float r0[512], r1[512];
    r0[d] = s0; r1[d] = s1;
    __syncthreads();
    for (int off = 256; off > 0; off >>= 1) {
        if (d < off) { r0[d] += r0[d + off]; r1[d] += r1[d + off]; }
        __syncthreads();
    }
    if (d == 0) {
        out[b*2 + 0] = r0[0] + ob[0];
        out[b*2 + 1] = r1[0] + ob[1];
    }
}

// ---------------- launch --------------------------------------------------------
extern "C" void kernel_launch(void* const* d_in, const int* in_sizes, int n_in,
                              void* d_out, int out_size) {
    const float* emb   = (const float*)d_in[0];
    const float* Wall  = (const float*)d_in[1];
    const float* Wallb = (const float*)d_in[2];
    const float* U     = (const float*)d_in[3];
    const float* Ub    = (const float*)d_in[4];
    const float* Wd    = (const float*)d_in[5];
    const float* Wdb   = (const float*)d_in[6];
    const float* selw  = (const float*)d_in[7];
    const float* selb  = (const float*)d_in[8];
    const float* timew = (const float*)d_in[9];
    const float* timeb = (const float*)d_in[10];
    const float* outw  = (const float*)d_in[11];
    const float* outb  = (const float*)d_in[12];
    const float* tstep = (const float*)d_in[13];
    const int*   seqs  = (const int*)d_in[14];
    float* out = (float*)d_out;

    static int configured = 0;
    if (!configured) {
        cudaFuncSetAttribute(k_rnn, cudaFuncAttributeMaxDynamicSharedMemorySize, STEP_SMEM);
        configured = 1;
    }

    k_zero<<<128, 256>>>();
    k_gather<<<BS, 128>>>(emb, seqs);
    k_tf<<<128, 512>>>(tstep, selw, selb, timew, timeb);
    k_gemm_ux<<<dim3(G4D/TN, BS/TM), 256>>>(U, Ub);
    k_rnn<<<NCTA, 512, STEP_SMEM>>>(Wall, Wallb, Wd, Wdb);
    k_pool<<<BB, 512>>>(outw, outb, out);
}

// round 11
// speedup vs baseline: 1.5557x; 1.5557x over previous
#include <cuda_runtime.h>
#include <cuda_bf16.h>
#include <math.h>

// Problem constants
#define BB 64
#define SS 128
#define CC 32
#define DD 512
#define VV 20000
#define BS (BB*SS)          // 8192
#define G4D (4*DD)          // 2048

// ---------------- device scratch (allocation-free rule: __device__ globals) ----
__device__ float g_x[BS*DD];           // 16 MB  visit embeddings summed
__device__ float g_tf[BS*DD];          // 16 MB  time features
__device__ float g_ux[(size_t)BS*G4D]; // 64 MB  input projection
__device__ float g_h[2][BB*DD];        // ping-pong hidden
__device__ float g_c[2][BB*DD];        // ping-pong cell
__device__ float g_hs[(size_t)BB*SS*DD]; // 16 MB all hidden states
__device__ unsigned g_flags[128];      // per-CTA step counters
__device__ unsigned g_release[2][32];  // per-group release words (padded)

// ---------------- f32x2 packed helpers (Blackwell) ----------------------------
__device__ __forceinline__ unsigned long long ffma2(unsigned long long a,
                                                    unsigned long long b,
                                                    unsigned long long c) {
    unsigned long long d;
    asm("fma.rn.f32x2 %0, %1, %2, %3;" : "=l"(d) : "l"(a), "l"(b), "l"(c));
    return d;
}
__device__ __forceinline__ unsigned long long pack2(float lo, float hi) {
    unsigned long long r;
    asm("mov.b64 %0, {%1, %2};" : "=l"(r) : "f"(lo), "f"(hi));
    return r;
}
__device__ __forceinline__ float2 unpack2(unsigned long long v) {
    float2 r;
    asm("mov.b64 {%0, %1}, %2;" : "=f"(r.x), "=f"(r.y) : "l"(v));
    return r;
}
union F4U { float4 f; unsigned long long u[2]; };

__device__ __forceinline__ float sigmoidf_(float x) { return 1.0f / (1.0f + expf(-x)); }

__device__ __forceinline__ void cpasync16(unsigned saddr, const float* g) {
    asm volatile("cp.async.cg.shared.global [%0], [%1], 16;" :: "r"(saddr), "l"(g));
}
__device__ __forceinline__ void cpasync_commit() {
    asm volatile("cp.async.commit_group;");
}
template<int N> __device__ __forceinline__ void cpasync_wait() {
    asm volatile("cp.async.wait_group %0;" :: "n"(N));
}

// ---------------- kernel: zero h0/c0 + reset barrier state ---------------------
__global__ void k_zero() {
    int i = blockIdx.x * blockDim.x + threadIdx.x;
    if (i < BB*DD) { g_h[0][i] = 0.0f; g_c[0][i] = 0.0f; }
    if (i < 128) g_flags[i] = 0u;
    if (i < 64) ((unsigned*)g_release)[i] = 0u;
}

// ---------------- kernel: gather + sum embeddings ------------------------------
__global__ __launch_bounds__(128) void k_gather(const float* __restrict__ emb,
                                                const int* __restrict__ seqs) {
    int bs = blockIdx.x;
    __shared__ int sidx[CC];
    if (threadIdx.x < CC) sidx[threadIdx.x] = seqs[bs*CC + threadIdx.x];
    __syncthreads();
    int d4 = threadIdx.x;  // 0..127
    float4 acc = make_float4(0.f, 0.f, 0.f, 0.f);
#pragma unroll 8
    for (int c = 0; c < CC; c++) {
        const float4* row = (const float4*)(emb + (size_t)sidx[c] * DD);
        float4 v = __ldg(row + d4);
        acc.x += v.x; acc.y += v.y; acc.z += v.z; acc.w += v.w;
    }
    ((float4*)(g_x + (size_t)bs * DD))[d4] = acc;
}

// ---------------- kernel: time feature ----------------------------------------
__global__ __launch_bounds__(512) void k_tf(const float* __restrict__ tstep,
                                            const float* __restrict__ selw,
                                            const float* __restrict__ selb,
                                            const float* __restrict__ timew,
                                            const float* __restrict__ timeb) {
    int b  = blockIdx.x >> 1;
    int s0 = (blockIdx.x & 1) * 64;
    int d  = threadIdx.x;
    float tw[64];
    const float4* twp = (const float4*)(timew + (size_t)d * 64);
#pragma unroll
    for (int i = 0; i < 16; i++) {
        float4 v = __ldg(twp + i);
        tw[i*4+0] = v.x; tw[i*4+1] = v.y; tw[i*4+2] = v.z; tw[i*4+3] = v.w;
    }
    float tb = timeb[d];
    __shared__ float feat[64];
    for (int si = 0; si < 64; si++) {
        int s = s0 + si;
        if (d < 64) {
            float t = tstep[b*SS + s] * (1.0f / 180.0f);
            float v = t * selw[d] + selb[d];
            feat[d] = 1.0f - tanhf(v * v);
        }
        __syncthreads();
        float acc = tb;
#pragma unroll
        for (int k = 0; k < 64; k++) acc += feat[k] * tw[k];
        g_tf[((size_t)b*SS + s) * DD + d] = acc;
        __syncthreads();
    }
}

// ---------------- kernel: ux = x @ U^T + Ub  (SGEMM 8192x2048x512, f32x2) ------
#define TM 128
#define TN 128
#define TK 16
__global__ __launch_bounds__(256, 2) void k_gemm_ux(const float* __restrict__ U,
                                                    const float* __restrict__ Ub) {
    __shared__ float As[2][TK][TM + 4];
    __shared__ float Bs[2][TK][TN + 4];
    int m0 = blockIdx.y * TM;
    int n0 = blockIdx.x * TN;
    int t = threadIdx.x;
    int lrow = t >> 2;          // 0..63
    int lcol = (t & 3) * 4;     // 0,4,8,12

    const float* Aptr = g_x + (size_t)(m0 + lrow) * DD + lcol;
    const float* Bptr = U   + (size_t)(n0 + lrow) * DD + lcol;

    float4 ra[2], rb[2];
    ra[0] = *(const float4*)(Aptr);
    ra[1] = *(const float4*)(Aptr + 64*DD);
    rb[0] = *(const float4*)(Bptr);
    rb[1] = *(const float4*)(Bptr + 64*DD);

    int warp = t >> 5;
    int wm   = warp >> 1;
    int wn   = warp & 1;
    int lane = t & 31;
    int lm   = lane >> 3;
    int ln   = lane & 7;
    int ma   = wm*32 + lm*4;
    int nb   = wn*64 + ln*4;

    unsigned long long acc[4][8];
#pragma unroll
    for (int mp = 0; mp < 4; mp++)
#pragma unroll
        for (int nn = 0; nn < 8; nn++) acc[mp][nn] = 0ull;

#pragma unroll
    for (int i = 0; i < 2; i++) {
        int r = lrow + i*64;
        As[0][lcol+0][r] = ra[i].x; As[0][lcol+1][r] = ra[i].y;
        As[0][lcol+2][r] = ra[i].z; As[0][lcol+3][r] = ra[i].w;
        Bs[0][lcol+0][r] = rb[i].x; Bs[0][lcol+1][r] = rb[i].y;
        Bs[0][lcol+2][r] = rb[i].z; Bs[0][lcol+3][r] = rb[i].w;
    }
    __syncthreads();

    const int NT = DD / TK;  // 32
    for (int kt = 0; kt < NT; kt++) {
        if (kt < NT - 1) {
            const float* ap = Aptr + (kt+1)*TK;
            const float* bp = Bptr + (kt+1)*TK;
            ra[0] = *(const float4*)(ap);
            ra[1] = *(const float4*)(ap + 64*DD);
            rb[0] = *(const float4*)(bp);
            rb[1] = *(const float4*)(bp + 64*DD);
        }
        int buf = kt & 1;
#pragma unroll
        for (int k = 0; k < TK; k++) {
            F4U a0, a1, b0, b1;
            a0.f = *(const float4*)&As[buf][k][ma];
            a1.f = *(const float4*)&As[buf][k][ma+16];
            b0.f = *(const float4*)&Bs[buf][k][nb];
            b1.f = *(const float4*)&Bs[buf][k][nb+32];
            unsigned long long ap2[4] = { a0.u[0], a0.u[1], a1.u[0], a1.u[1] };
            float bv[8] = {b0.f.x,b0.f.y,b0.f.z,b0.f.w,b1.f.x,b1.f.y,b1.f.z,b1.f.w};
            unsigned long long bb2[8];
#pragma unroll
            for (int nn = 0; nn < 8; nn++) bb2[nn] = pack2(bv[nn], bv[nn]);
#pragma unroll
            for (int mp = 0; mp < 4; mp++)
#pragma unroll
                for (int nn = 0; nn < 8; nn++)
                    acc[mp][nn] = ffma2(ap2[mp], bb2[nn], acc[mp][nn]);
        }
        if (kt < NT - 1) {
            __syncthreads();
            int nbuf = buf ^ 1;
#pragma unroll
            for (int i = 0; i < 2; i++) {
                int r = lrow + i*64;
                As[nbuf][lcol+0][r] = ra[i].x; As[nbuf][lcol+1][r] = ra[i].y;
                As[nbuf][lcol+2][r] = ra[i].z; As[nbuf][lcol+3][r] = ra[i].w;
                Bs[nbuf][lcol+0][r] = rb[i].x; Bs[nbuf][lcol+1][r] = rb[i].y;
                Bs[nbuf][lcol+2][r] = rb[i].z; Bs[nbuf][lcol+3][r] = rb[i].w;
            }
            __syncthreads();
        }
    }

    float ub[8];
#pragma unroll
    for (int nn = 0; nn < 8; nn++)
        ub[nn] = Ub[n0 + nb + (nn>>2)*32 + (nn&3)];
#pragma unroll
    for (int mp = 0; mp < 4; mp++) {
#pragma unroll
        for (int e = 0; e < 2; e++) {
            int m = m0 + ma + (mp>>1)*16 + (mp&1)*2 + e;
            float* Crow = g_ux + (size_t)m * G4D + n0;
#pragma unroll
            for (int nc = 0; nc < 2; nc++) {
                float4 v;
                float2 p0 = unpack2(acc[mp][nc*4+0]);
                float2 p1 = unpack2(acc[mp][nc*4+1]);
                float2 p2 = unpack2(acc[mp][nc*4+2]);
                float2 p3 = unpack2(acc[mp][nc*4+3]);
                v.x = (e ? p0.y : p0.x) + ub[nc*4+0];
                v.y = (e ? p1.y : p1.x) + ub[nc*4+1];
                v.z = (e ? p2.y : p2.x) + ub[nc*4+2];
                v.w = (e ? p3.y : p3.x) + ub[nc*4+3];
                *(float4*)(Crow + nb + nc*32) = v;
            }
        }
    }
}

// ---------------- persistent recurrent kernel (all 128 steps) -------------------
// 128 CTAs = 64 jg x 2 bg. CTA = 8 j x 32 b -> 40 output rows (5 gates x 8 j).
// Register-tiled: thread (kq,rq,bq) computes rows r=rq+4i (i<10) x 4 batch rows
// b=bq+8ib over its warp's k-slice [kq*64,kq*64+64). LDS.64 k-pairs feed 40
// FFMA2 per k2 -> 1.8 B/FMA vs 5.6 before (smem return-bw was the binding
// resource). Per-warp cp.async of own k-slice (no CTA sync in load path).
// k-partials reduced via smem; epilogue thread = one (b,j).
// HPAD=524: row stride 2096 B, 16B-aligned for cp.async (522 trapped: 2088%16=8).
#define NCTA 128
#define JPC 8
#define BPC 32
#define WROWS 40
#define WPAD 516
#define HPAD 524
#define RSTR 41
#define RNN_SMEM ((WROWS*WPAD + 2*BPC*HPAD) * 4)   // 216704 B

__global__ __launch_bounds__(256) void k_rnn(
        const float* __restrict__ Wall, const float* __restrict__ Wallb,
        const float* __restrict__ Wd,   const float* __restrict__ Wdb) {
    extern __shared__ float sm[];
    float* W  = sm;                       // 40 x 516
    float* HS = W + WROWS*WPAD;           // 32 x 524
    float* CS = HS + BPC*HPAD;            // 32 x 524
    unsigned long long* red = (unsigned long long*)HS;  // aliases HS(+CS head)

    unsigned HSu = (unsigned)__cvta_generic_to_shared(HS);
    unsigned CSu = (unsigned)__cvta_generic_to_shared(CS);

    int t    = threadIdx.x;
    int lane = t & 31;
    int kq   = t >> 5;          // warp id = k-slice 0..7
    int rq   = (t >> 3) & 3;    // row group
    int bq   = t & 7;           // batch group
    int jg = blockIdx.x & 63;
    int bg = blockIdx.x >> 6;
    int j0 = jg * JPC;
    int b0 = bg * BPC;

    // ---- weights: warp kq loads its own k-slice of all 40 rows (once) ----
    // rows r = g*8+jj: g<4 from Wall, g=4 from Wd
#pragma unroll
    for (int i = 0; i < 20; i++) {
        int lin = i*32 + lane;            // 0..639
        int row = lin >> 4, c4 = lin & 15;
        int g = row >> 3, jj2 = row & 7;
        const float* src = (g < 4)
            ? Wall + (size_t)(g*DD + j0 + jj2) * DD + kq*64 + c4*4
            : Wd   + (size_t)(j0 + jj2) * DD + kq*64 + c4*4;
        *(float4*)(W + row*WPAD + kq*64 + c4*4) = *(const float4*)src;
    }
    __syncwarp();

    // epilogue mapping: thread t -> (b_e, jj_e)
    int b_e  = t >> 3;          // 0..31
    int jj_e = t & 7;
    int gb_e = b0 + b_e;
    int j_e  = j0 + jj_e;

    float wdb  = __ldg(Wdb + j_e);
    float wab0 = __ldg(Wallb + 0*DD + j_e);
    float wab1 = __ldg(Wallb + 1*DD + j_e);
    float wab2 = __ldg(Wallb + 2*DD + j_e);
    float wab3 = __ldg(Wallb + 3*DD + j_e);

    // prefetch step-0 tf/ux
    float tfv = __ldg(g_tf + ((size_t)gb_e * SS + 0) * DD + j_e);
    float ux0 = __ldg(g_ux + ((size_t)gb_e * SS + 0) * G4D + 0*DD + j_e);
    float ux1 = __ldg(g_ux + ((size_t)gb_e * SS + 0) * G4D + 1*DD + j_e);
    float ux2 = __ldg(g_ux + ((size_t)gb_e * SS + 0) * G4D + 2*DD + j_e);
    float ux3 = __ldg(g_ux + ((size_t)gb_e * SS + 0) * G4D + 3*DD + j_e);

    for (int s = 0; s < SS; s++) {
        const float* h_in = g_h[s & 1];
        const float* c_in = g_c[s & 1];
        float* h_out = g_h[(s + 1) & 1];
        float* c_out = g_c[(s + 1) & 1];
        size_t bsoff = ((size_t)gb_e * SS + s);

        // ---- per-warp cp.async: own k-slice of h/c, 2 halves (double buffer) ----
#pragma unroll
        for (int hh = 0; hh < 2; hh++) {
#pragma unroll
            for (int i = 0; i < 8; i++) {
                int lin = i*32 + lane;    // 0..255
                int row = lin >> 3, c4 = lin & 7;
                int col = kq*64 + hh*32 + c4*4;
                unsigned so = (unsigned)((row*HPAD + col) * 4);
                cpasync16(HSu + so, h_in + (size_t)(b0+row)*DD + col);
                cpasync16(CSu + so, c_in + (size_t)(b0+row)*DD + col);
            }
            cpasync_commit();
        }

        unsigned long long acc[10][4];
#pragma unroll
        for (int i = 0; i < 10; i++)
#pragma unroll
            for (int ib = 0; ib < 4; ib++) acc[i][ib] = 0ull;

        // ---- compute: rows r=rq+4i, batch b=bq+8ib, own k-slice ----
#pragma unroll
        for (int hh = 0; hh < 2; hh++) {
            if (hh == 0) cpasync_wait<1>(); else cpasync_wait<0>();
            __syncwarp();
#pragma unroll 2
            for (int mm = 0; mm < 16; mm++) {
                int off = kq*64 + hh*32 + mm*2;
                unsigned long long hp[4], cp[4], wp[10];
#pragma unroll
                for (int ib = 0; ib < 4; ib++) {
                    hp[ib] = *(const unsigned long long*)(HS + (bq + 8*ib)*HPAD + off);
                    cp[ib] = *(const unsigned long long*)(CS + (bq + 8*ib)*HPAD + off);
                }
#pragma unroll
                for (int i = 0; i < 10; i++)
                    wp[i] = *(const unsigned long long*)(W + (rq + 4*i)*WPAD + off);
#pragma unroll
                for (int i = 0; i < 10; i++) {
#pragma unroll
                    for (int ib = 0; ib < 4; ib++) {
                        unsigned long long srcv = (i < 8) ? hp[ib] : cp[ib];
                        acc[i][ib] = ffma2(srcv, wp[i], acc[i][ib]);
                    }
                }
            }
        }

        __syncthreads();                 // all warps' compute done; CS fully valid
        float cprev = CS[b_e*HPAD + j_e];
        __syncthreads();                 // cprev reads done before red overwrites

        // ---- store k-partials ----
#pragma unroll
        for (int i = 0; i < 10; i++)
#pragma unroll
            for (int ib = 0; ib < 4; ib++)
                red[t*RSTR + i*4 + ib] = acc[i][ib];
        __syncthreads();

        // ---- gather + pointwise: thread owns (b_e, j_e), all 5 gates ----
        float gate[5];
        int bqp = b_e & 7, ibp = b_e >> 3;
#pragma unroll
        for (int g = 0; g < 5; g++) {
            int r = g*8 + jj_e;
            int rqp = r & 3, ip = r >> 2;
            float sx = 0.f, sy = 0.f;
#pragma unroll
            for (int kk = 0; kk < 8; kk++) {
                float2 p = unpack2(red[(kk*32 + rqp*8 + bqp)*RSTR + ip*4 + ibp]);
                sx += p.x; sy += p.y;
            }
            gate[g] = sx + sy;
        }

        float cs1 = tanhf(gate[4] + wdb);
        float fg = sigmoidf_(gate[0] + wab0 + ux0);
        float ig = sigmoidf_(gate[1] + wab1 + ux1);
        float og = sigmoidf_(gate[2] + wab2 + ux2);
        float ct = sigmoidf_(gate[3] + wab3 + ux3);

        float cadj = cprev + cs1 * (tfv - 1.0f);
        float cn   = fg * cadj + ig * ct;
        float hn   = og * tanhf(cn);
        c_out[(size_t)gb_e*DD + j_e] = cn;
        h_out[(size_t)gb_e*DD + j_e] = hn;
        g_hs[bsoff * DD + j_e] = hn;

        if (s < SS - 1) {
            // prefetch next step's tf/ux (hidden under barrier)
            size_t bsoff1 = bsoff + 1;
            tfv = __ldg(g_tf + bsoff1 * DD + j_e);
            const float* uxr1 = g_ux + bsoff1 * G4D;
            ux0 = __ldg(uxr1 + 0*DD + j_e);
            ux1 = __ldg(uxr1 + 1*DD + j_e);
            ux2 = __ldg(uxr1 + 2*DD + j_e);
            ux3 = __ldg(uxr1 + 3*DD + j_e);

            // ---- half-grid barrier for group bg (64 CTAs), no atomics ----
            __syncthreads();
            if (t == 0) {
                __threadfence();
                *(volatile unsigned*)&g_flags[blockIdx.x] = (unsigned)(s + 1);
            }
            if (jg == 0) {
                if (t < 64) {
                    const volatile unsigned* f = (const volatile unsigned*)&g_flags[bg*64 + t];
                    while (*f < (unsigned)(s + 1)) { }
                    __threadfence();
                }
                __syncthreads();
                if (t == 0) {
                    *(volatile unsigned*)&g_release[bg][0] = (unsigned)(s + 1);
                }
            } else {
                if (t == 0) {
                    const volatile unsigned* r = (const volatile unsigned*)&g_release[bg][0];
                    while (*r < (unsigned)(s + 1)) { }
                    __threadfence();
                }
                __syncthreads();
            }
        }
    }
}

// ---------------- kernel: max-pool over S + output head ------------------------
__global__ __launch_bounds__(512) void k_pool(const float* __restrict__ ow,
                                              const float* __restrict__ ob,
                                              float* __restrict__ out) {
    int b = blockIdx.x;
    int d = threadIdx.x;
    const float* p = g_hs + (size_t)b * SS * DD + d;
    float m = -3.0e38f;
#pragma unroll 8
    for (int s = 0; s < SS; s++) m = fmaxf(m, p[(size_t)s * DD]);
    float s0 = m * ow[d];
    float s1 = m * ow[DD + d];
    __shared__ float r0[512], r1[512];
    r0[d] = s0; r1[d] = s1;
    __syncthreads();
    for (int off = 256; off > 0; off >>= 1) {
        if (d < off) { r0[d] += r0[d + off]; r1[d] += r1[d + off]; }
        __syncthreads();
    }
    if (d == 0) {
        out[b*2 + 0] = r0[0] + ob[0];
        out[b*2 + 1] = r1[0] + ob[1];
    }
}

// ---------------- launch --------------------------------------------------------
extern "C" void kernel_launch(void* const* d_in, const int* in_sizes, int n_in,
                              void* d_out, int out_size) {
    const float* emb   = (const float*)d_in[0];
    const float* Wall  = (const float*)d_in[1];
    const float* Wallb = (const float*)d_in[2];
    const float* U     = (const float*)d_in[3];
    const float* Ub    = (const float*)d_in[4];
    const float* Wd    = (const float*)d_in[5];
    const float* Wdb   = (const float*)d_in[6];
    const float* selw  = (const float*)d_in[7];
    const float* selb  = (const float*)d_in[8];
    const float* timew = (const float*)d_in[9];
    const float* timeb = (const float*)d_in[10];
    const float* outw  = (const float*)d_in[11];
    const float* outb  = (const float*)d_in[12];
    const float* tstep = (const float*)d_in[13];
    const int*   seqs  = (const int*)d_in[14];
    float* out = (float*)d_out;

    static int configured = 0;
    if (!configured) {
        cudaFuncSetAttribute(k_rnn, cudaFuncAttributeMaxDynamicSharedMemorySize, RNN_SMEM);
        configured = 1;
    }

    k_zero<<<128, 256>>>();
    k_gather<<<BS, 128>>>(emb, seqs);
    k_tf<<<128, 512>>>(tstep, selw, selb, timew, timeb);
    k_gemm_ux<<<dim3(G4D/TN, BS/TM), 256>>>(U, Ub);
    k_rnn<<<NCTA, 256, RNN_SMEM>>>(Wall, Wallb, Wd, Wdb);
    k_pool<<<BB, 512>>>(outw, outb, out);
}